// round 1
// baseline (speedup 1.0000x reference)
#include <cuda_runtime.h>
#include <cstdint>

#define B_TOTAL   65536
#define QD        512
#define KD        64
#define NAUX      8
#define LN_EPS    1e-5f
#define ROWS      64          // rows per block
#define THREADS   256         // 4 threads per row, 16 cols each
#define NCHUNK    (QD / 64)   // 8 chunks of the M matrix

typedef unsigned long long u64;

// ---------------- f32x2 packed-math helpers (Blackwell sm_103a) ----------------
__device__ __forceinline__ u64 ffma2(u64 a, u64 b, u64 c) {
    u64 d;
    asm("fma.rn.f32x2 %0, %1, %2, %3;" : "=l"(d) : "l"(a), "l"(b), "l"(c));
    return d;
}
__device__ __forceinline__ u64 pack2(float lo, float hi) {
    u64 r;
    asm("mov.b64 %0, {%1, %2};" : "=l"(r) : "f"(lo), "f"(hi));
    return r;
}
__device__ __forceinline__ void unpack2(u64 v, float& lo, float& hi) {
    asm("mov.b64 {%0, %1}, %2;" : "=f"(lo), "=f"(hi) : "l"(v));
}

// Scratch for M = W_q^T @ W_k  (512 x 64 row-major), 128 KB device global.
__device__ float g_M[QD * KD];

// ---------------- Kernel 1: M[i][j] = sum_e w_q[e,i] * w_k[e,j] ----------------
__global__ void lca_compute_M(const float* __restrict__ w_q,
                              const float* __restrict__ w_k) {
    const int i = blockIdx.x;    // 0..511
    const int j = threadIdx.x;   // 0..63
    float acc = 0.0f;
#pragma unroll 8
    for (int e = 0; e < KD; ++e)
        acc = fmaf(w_q[e * QD + i], w_k[e * KD + j], acc);
    g_M[i * KD + j] = acc;
}

// ---------------- Kernel 2: fused attention + layernorm ----------------
// Smem layout (floats):
//   sM    [64*64]   = 4096    : current 64-row chunk of M
//   sQt   [64*65]   = 4160    : transposed query chunk, pitch 65 (bank-conflict free)
//   sWvT  [64*64]   = 4096    : W_v transposed -> sWvT[d*64+e] = w_v[e*64+d]
//   sS    [64*65]   = 4160    : per-row weighted kv sum s[d], pitch 65
// total = 16512 floats = 66048 bytes (dynamic smem)
__global__ void __launch_bounds__(THREADS, 3)
lca_main(const float* __restrict__ query,
         const float* __restrict__ kv,
         const float* __restrict__ w_v,
         const float* __restrict__ gamma,
         const float* __restrict__ beta,
         float* __restrict__ out) {
    extern __shared__ float smem[];
    float* sM   = smem;                 // 4096
    float* sQt  = smem + 4096;          // 4160
    float* sWvT = smem + 8256;          // 4096
    float* sS   = smem + 12352;         // 4160

    const int tid = threadIdx.x;
    const int sub = tid & 3;            // 4 threads per row
    const int row = tid >> 2;           // local row 0..63
    const int c0  = sub * 16;           // this thread's 16 columns
    const int b0  = blockIdx.x * ROWS;
    const int b   = b0 + row;

    // Stage W_v transposed (one-time per block)
    for (int idx = tid; idx < KD * KD; idx += THREADS) {
        int e = idx >> 6, d = idx & 63;
        sWvT[d * KD + e] = w_v[idx];
    }

    // ---------------- Stage 1: qm = query @ M  (f32x2 packed) ----------------
    u64 acc[8];
#pragma unroll
    for (int k = 0; k < 8; ++k) acc[k] = 0ull;

    for (int chunk = 0; chunk < NCHUNK; ++chunk) {
        const int i0 = chunk * 64;
        __syncthreads();  // protect previous chunk reads before overwrite

        // load M chunk: contiguous 4096 floats
        {
            const float4* src = (const float4*)(g_M + i0 * KD);
            float4* dst = (float4*)sM;
            for (int idx = tid; idx < 1024; idx += THREADS) dst[idx] = src[idx];
        }
        // load query chunk transposed: sQt[ii*65 + r] = query[b0+r][i0+ii]
#pragma unroll
        for (int p = 0; p < 4; ++p) {
            int idx = p * THREADS + tid;          // 0..1023
            int r   = idx >> 4;                   // 0..63
            int cc  = (idx & 15) << 2;            // 0,4,...,60
            float4 q4 = *(const float4*)(query + (size_t)(b0 + r) * QD + i0 + cc);
            sQt[(cc + 0) * 65 + r] = q4.x;
            sQt[(cc + 1) * 65 + r] = q4.y;
            sQt[(cc + 2) * 65 + r] = q4.z;
            sQt[(cc + 3) * 65 + r] = q4.w;
        }
        __syncthreads();

        const u64* sMd = (const u64*)sM;
#pragma unroll 8
        for (int ii = 0; ii < 64; ++ii) {
            float qv = sQt[ii * 65 + row];        // broadcast across subs
            u64 qq = pack2(qv, qv);
            const u64* mrow = sMd + ii * 32 + (c0 >> 1);
#pragma unroll
            for (int k = 0; k < 8; ++k)
                acc[k] = ffma2(qq, mrow[k], acc[k]);
        }
    }

    float qm[16];
#pragma unroll
    for (int k = 0; k < 8; ++k) unpack2(acc[k], qm[2 * k], qm[2 * k + 1]);

    // ---------------- Stage 2: scores[n] = (qm . kv[b,n]) * 0.125 ----------------
    const float4* kvp = (const float4*)(kv + (size_t)b * (NAUX * KD) + c0);
    float sc[NAUX];
#pragma unroll
    for (int n = 0; n < NAUX; ++n) {
        float4 a0 = kvp[n * 16 + 0];
        float4 a1 = kvp[n * 16 + 1];
        float4 a2 = kvp[n * 16 + 2];
        float4 a3 = kvp[n * 16 + 3];
        float p = 0.0f;
        p = fmaf(a0.x, qm[0], p);  p = fmaf(a0.y, qm[1], p);
        p = fmaf(a0.z, qm[2], p);  p = fmaf(a0.w, qm[3], p);
        p = fmaf(a1.x, qm[4], p);  p = fmaf(a1.y, qm[5], p);
        p = fmaf(a1.z, qm[6], p);  p = fmaf(a1.w, qm[7], p);
        p = fmaf(a2.x, qm[8], p);  p = fmaf(a2.y, qm[9], p);
        p = fmaf(a2.z, qm[10], p); p = fmaf(a2.w, qm[11], p);
        p = fmaf(a3.x, qm[12], p); p = fmaf(a3.y, qm[13], p);
        p = fmaf(a3.z, qm[14], p); p = fmaf(a3.w, qm[15], p);
        sc[n] = p;
    }
    // reduce partial dot products across the 4 subs (same warp)
#pragma unroll
    for (int n = 0; n < NAUX; ++n) {
        sc[n] += __shfl_xor_sync(0xffffffffu, sc[n], 1);
        sc[n] += __shfl_xor_sync(0xffffffffu, sc[n], 2);
        sc[n] *= 0.125f;   // KV_DIM^-0.5
    }

    // softmax over 8 (redundant in each of the 4 subs; cheap)
    float mx = sc[0];
#pragma unroll
    for (int n = 1; n < NAUX; ++n) mx = fmaxf(mx, sc[n]);
    float attn[NAUX];
    float ssum = 0.0f;
#pragma unroll
    for (int n = 0; n < NAUX; ++n) { attn[n] = expf(sc[n] - mx); ssum += attn[n]; }
    float rs = 1.0f / ssum;
#pragma unroll
    for (int n = 0; n < NAUX; ++n) attn[n] *= rs;

    // ---------------- Stage 3: s[d] = sum_n attn[n] * kv[b,n,d] ----------------
    float s16[16];
#pragma unroll
    for (int k = 0; k < 16; ++k) s16[k] = 0.0f;
#pragma unroll
    for (int n = 0; n < NAUX; ++n) {
        float w = attn[n];
        float4 a0 = kvp[n * 16 + 0];   // L1 hit (just touched in stage 2)
        float4 a1 = kvp[n * 16 + 1];
        float4 a2 = kvp[n * 16 + 2];
        float4 a3 = kvp[n * 16 + 3];
        s16[0]  = fmaf(w, a0.x, s16[0]);  s16[1]  = fmaf(w, a0.y, s16[1]);
        s16[2]  = fmaf(w, a0.z, s16[2]);  s16[3]  = fmaf(w, a0.w, s16[3]);
        s16[4]  = fmaf(w, a1.x, s16[4]);  s16[5]  = fmaf(w, a1.y, s16[5]);
        s16[6]  = fmaf(w, a1.z, s16[6]);  s16[7]  = fmaf(w, a1.w, s16[7]);
        s16[8]  = fmaf(w, a2.x, s16[8]);  s16[9]  = fmaf(w, a2.y, s16[9]);
        s16[10] = fmaf(w, a2.z, s16[10]); s16[11] = fmaf(w, a2.w, s16[11]);
        s16[12] = fmaf(w, a3.x, s16[12]); s16[13] = fmaf(w, a3.y, s16[13]);
        s16[14] = fmaf(w, a3.z, s16[14]); s16[15] = fmaf(w, a3.w, s16[15]);
    }

    // publish s to smem (full 64-vector per row needed for the W_v matvec)
#pragma unroll
    for (int k = 0; k < 16; ++k) sS[row * 65 + c0 + k] = s16[k];
    __syncthreads();

    // ---------------- Stage 4: o[e] = sum_d w_v[e,d] * s[d]  (f32x2) ----------------
    u64 oacc[8];
#pragma unroll
    for (int k = 0; k < 8; ++k) oacc[k] = 0ull;
    const u64* sWvTd = (const u64*)sWvT;
#pragma unroll 8
    for (int d = 0; d < KD; ++d) {
        float sv = sS[row * 65 + d];
        u64 ss = pack2(sv, sv);
        const u64* wrow = sWvTd + d * 32 + (c0 >> 1);
#pragma unroll
        for (int k = 0; k < 8; ++k)
            oacc[k] = ffma2(ss, wrow[k], oacc[k]);
    }
    float ov[16];
#pragma unroll
    for (int k = 0; k < 8; ++k) unpack2(oacc[k], ov[2 * k], ov[2 * k + 1]);

    // ---------------- Stage 5: LayerNorm over 64 ----------------
    float lsum = 0.0f, lsq = 0.0f;
#pragma unroll
    for (int k = 0; k < 16; ++k) { lsum += ov[k]; lsq = fmaf(ov[k], ov[k], lsq); }
    lsum += __shfl_xor_sync(0xffffffffu, lsum, 1);
    lsum += __shfl_xor_sync(0xffffffffu, lsum, 2);
    lsq  += __shfl_xor_sync(0xffffffffu, lsq, 1);
    lsq  += __shfl_xor_sync(0xffffffffu, lsq, 2);
    const float mean = lsum * (1.0f / 64.0f);
    const float var  = lsq * (1.0f / 64.0f) - mean * mean;
    const float inv  = rsqrtf(var + LN_EPS);

    float res[16];
#pragma unroll
    for (int k = 0; k < 16; ++k) {
        float g = gamma[c0 + k];
        float be = beta[c0 + k];
        res[k] = fmaf((ov[k] - mean) * inv, g, be);
    }
    float4* op = (float4*)(out + (size_t)b * KD + c0);
    op[0] = make_float4(res[0],  res[1],  res[2],  res[3]);
    op[1] = make_float4(res[4],  res[5],  res[6],  res[7]);
    op[2] = make_float4(res[8],  res[9],  res[10], res[11]);
    op[3] = make_float4(res[12], res[13], res[14], res[15]);
}

// ---------------- launch ----------------
extern "C" void kernel_launch(void* const* d_in, const int* in_sizes, int n_in,
                              void* d_out, int out_size) {
    const float* query = (const float*)d_in[0];
    const float* kv    = (const float*)d_in[1];
    const float* w_q   = (const float*)d_in[2];
    const float* w_k   = (const float*)d_in[3];
    const float* w_v   = (const float*)d_in[4];
    const float* gamma = (const float*)d_in[5];
    const float* beta  = (const float*)d_in[6];
    float* out = (float*)d_out;

    const int smem_bytes = 16512 * sizeof(float);   // 66048
    cudaFuncSetAttribute(lca_main, cudaFuncAttributeMaxDynamicSharedMemorySize, smem_bytes);

    lca_compute_M<<<QD, KD>>>(w_q, w_k);
    lca_main<<<B_TOTAL / ROWS, THREADS, smem_bytes>>>(query, kv, w_v, gamma, beta, out);
}

// round 2
// speedup vs baseline: 3.9798x; 3.9798x over previous
#include <cuda_runtime.h>
#include <cstdint>

#define QD        512
#define KD        64
#define NAUX      8
#define B_TOTAL   65536
#define LN_EPS    1e-5f

#define RB        256        // batch rows per block
#define THREADS   256
#define IC        32         // i-chunk size
#define NCH       (QD / IC)  // 16 chunks
#define QP        264        // sQ pitch (floats)

typedef unsigned long long u64;

// ---------------- f32x2 packed-math helpers (sm_103a) ----------------
__device__ __forceinline__ u64 ffma2(u64 a, u64 b, u64 c) {
    u64 d;
    asm("fma.rn.f32x2 %0, %1, %2, %3;" : "=l"(d) : "l"(a), "l"(b), "l"(c));
    return d;
}
__device__ __forceinline__ u64 pack2(float lo, float hi) {
    u64 r;
    asm("mov.b64 %0, {%1, %2};" : "=l"(r) : "f"(lo), "f"(hi));
    return r;
}
__device__ __forceinline__ void unpack2(u64 v, float& lo, float& hi) {
    asm("mov.b64 {%0, %1}, %2;" : "=f"(lo), "=f"(hi) : "l"(v));
}

// M = W_q^T @ W_k  (512 x 64 row-major), 128 KB scratch.
__device__ float g_M[QD * KD];

__global__ void lca_compute_M(const float* __restrict__ w_q,
                              const float* __restrict__ w_k) {
    const int i = blockIdx.x;    // 0..511
    const int j = threadIdx.x;   // 0..63
    float acc = 0.0f;
#pragma unroll 8
    for (int e = 0; e < KD; ++e)
        acc = fmaf(w_q[e * QD + i], w_k[e * KD + j], acc);
    g_M[i * KD + j] = acc;
}

// Smem (floats), two overlapping phases:
//  Phase A: sQ [IC*QP = 8448]  |  sM dup copies [4100]  (total 12548)
//  Phase B: sQM 256x68 = 17408 (aliases phase A)  |  sWvT 64x68 = 4352 @17408
//  sS aliases sQM row-for-row.
#define SMEM_FLOATS 21760

__global__ void __launch_bounds__(THREADS, 2)
lca_main(const float* __restrict__ query,
         const float* __restrict__ kv,
         const float* __restrict__ w_v,
         const float* __restrict__ gamma,
         const float* __restrict__ beta,
         float* __restrict__ out) {
    extern __shared__ float smem[];
    float* sQ   = smem;                  // phase A
    float* sM   = smem + IC * QP;        // phase A (dup copies: +0 and +2052)
    float* sQM  = smem;                  // phase B (aliases A)
    float* sWvT = smem + 17408;          // persistent
    float* sS   = smem;                  // aliases sQM, row-exact

    const int tid = threadIdx.x;
    const int ct  = tid & 7;             // col group: cols ct*8 .. ct*8+7
    const int rt  = tid >> 3;            // row group: rows rt*8 .. rt*8+7
    const int b0  = blockIdx.x * RB;

    // Fill sWvT (transposed W_v, pitch 68) once; visible after first barrier.
    for (int idx = tid; idx < KD * KD; idx += THREADS) {
        int e = idx >> 6, d = idx & 63;
        sWvT[d * 68 + e] = w_v[idx];
    }

    // ---------------- Stage 1: qm = query @ M ----------------
    u64 acc[8][4];
#pragma unroll
    for (int r = 0; r < 8; ++r)
#pragma unroll
        for (int c = 0; c < 4; ++c) acc[r][c] = 0ull;

    const float* sMb = sM + (ct >> 2) * 2052 + ct * 8;

    for (int ch = 0; ch < NCH; ++ch) {
        const int i0 = ch * IC;
        __syncthreads();

        // Load M chunk (32x64), duplicated at +2052 for conflict-free ct>=4 reads
        {
            const float4* src = (const float4*)(g_M + i0 * KD);
            float4* d0 = (float4*)sM;
            float4* d1 = (float4*)(sM + 2052);
#pragma unroll
            for (int p = 0; p < 2; ++p) {
                int idx = p * THREADS + tid;     // 0..511
                float4 v = src[idx];
                d0[idx] = v; d1[idx] = v;
            }
        }
        // Load query chunk transposed + swizzled: sQ[ii][r ^ ((ii>>2)<<3)]
#pragma unroll
        for (int p = 0; p < 8; ++p) {
            int idx = p * THREADS + tid;         // 0..2047
            int r   = idx >> 3;                  // 0..255
            int c4  = idx & 7;                   // ii quad
            float4 q4 = *(const float4*)(query + (size_t)(b0 + r) * QD + i0 + c4 * 4);
            int rs = r ^ (c4 << 3);
            sQ[(c4 * 4 + 0) * QP + rs] = q4.x;
            sQ[(c4 * 4 + 1) * QP + rs] = q4.y;
            sQ[(c4 * 4 + 2) * QP + rs] = q4.z;
            sQ[(c4 * 4 + 3) * QP + rs] = q4.w;
        }
        __syncthreads();

#pragma unroll 8
        for (int ii = 0; ii < IC; ++ii) {
            const float* qb = sQ + ii * QP + ((rt * 8) ^ (((ii >> 2) & 7) << 3));
            float4 qa = *(const float4*)qb;
            float4 qc = *(const float4*)(qb + 4);
            const float4* mp = (const float4*)(sMb + ii * KD);
            float4 ma = mp[0], mb = mp[1];
            u64 m0 = pack2(ma.x, ma.y), m1 = pack2(ma.z, ma.w);
            u64 m2 = pack2(mb.x, mb.y), m3 = pack2(mb.z, mb.w);
            float qr[8] = {qa.x, qa.y, qa.z, qa.w, qc.x, qc.y, qc.z, qc.w};
#pragma unroll
            for (int r = 0; r < 8; ++r) {
                u64 qq = pack2(qr[r], qr[r]);
                acc[r][0] = ffma2(qq, m0, acc[r][0]);
                acc[r][1] = ffma2(qq, m1, acc[r][1]);
                acc[r][2] = ffma2(qq, m2, acc[r][2]);
                acc[r][3] = ffma2(qq, m3, acc[r][3]);
            }
        }
    }
    __syncthreads();   // all reads of sQ/sM done; safe to overwrite with sQM

    // Hand off qm to smem (pitch 68)
#pragma unroll
    for (int r = 0; r < 8; ++r) {
        float4 v0, v1;
        unpack2(acc[r][0], v0.x, v0.y); unpack2(acc[r][1], v0.z, v0.w);
        unpack2(acc[r][2], v1.x, v1.y); unpack2(acc[r][3], v1.z, v1.w);
        float* dst = sQM + (rt * 8 + r) * 68 + ct * 8;
        *(float4*)dst       = v0;
        *(float4*)(dst + 4) = v1;
    }
    __syncthreads();

    // ---------------- Epilogue: attention + W_v + LayerNorm ----------------
    // 4 threads/row; thread's cols: c(m,e) = sub*4 + m*16 + e  (interleaved)
    const int sub   = tid & 3;
    const int row64 = tid >> 2;

    // Stages 2+3 for rows g*64+row64, g=0..3. sS[r] overwrites sQM[r] (safe:
    // row r's qm is read only by row r's own 4 sub-threads before the write).
    for (int g = 0; g < 4; ++g) {
        const int r = g * 64 + row64;
        const size_t b = b0 + r;

        float4 qmv[4];
#pragma unroll
        for (int m = 0; m < 4; ++m)
            qmv[m] = *(const float4*)(sQM + r * 68 + sub * 4 + m * 16);

        const float* kvb = kv + b * (NAUX * KD) + sub * 4;

        float sc[NAUX];
#pragma unroll
        for (int n = 0; n < NAUX; ++n) {
            float p = 0.0f;
#pragma unroll
            for (int m = 0; m < 4; ++m) {
                float4 a = *(const float4*)(kvb + n * KD + m * 16);
                p = fmaf(a.x, qmv[m].x, p);
                p = fmaf(a.y, qmv[m].y, p);
                p = fmaf(a.z, qmv[m].z, p);
                p = fmaf(a.w, qmv[m].w, p);
            }
            sc[n] = p;
        }
#pragma unroll
        for (int n = 0; n < NAUX; ++n) {
            sc[n] += __shfl_xor_sync(0xffffffffu, sc[n], 1);
            sc[n] += __shfl_xor_sync(0xffffffffu, sc[n], 2);
            sc[n] *= 0.125f;           // KV_DIM^-0.5
        }
        float mx = sc[0];
#pragma unroll
        for (int n = 1; n < NAUX; ++n) mx = fmaxf(mx, sc[n]);
        float attn[NAUX], ssum = 0.0f;
#pragma unroll
        for (int n = 0; n < NAUX; ++n) { attn[n] = __expf(sc[n] - mx); ssum += attn[n]; }
        float rs = 1.0f / ssum;

        float s16[4][4];
#pragma unroll
        for (int m = 0; m < 4; ++m)
#pragma unroll
            for (int e = 0; e < 4; ++e) s16[m][e] = 0.0f;
#pragma unroll
        for (int n = 0; n < NAUX; ++n) {
            float w = attn[n] * rs;
#pragma unroll
            for (int m = 0; m < 4; ++m) {
                float4 a = *(const float4*)(kvb + n * KD + m * 16);   // L1 hit
                s16[m][0] = fmaf(w, a.x, s16[m][0]);
                s16[m][1] = fmaf(w, a.y, s16[m][1]);
                s16[m][2] = fmaf(w, a.z, s16[m][2]);
                s16[m][3] = fmaf(w, a.w, s16[m][3]);
            }
        }
#pragma unroll
        for (int m = 0; m < 4; ++m)
            *(float4*)(sS + r * 68 + sub * 4 + m * 16) =
                make_float4(s16[m][0], s16[m][1], s16[m][2], s16[m][3]);
    }
    __syncwarp();   // sS rows of this warp's threads all written

    // Stage 4: o = W_v @ s for all 4 rows at once (reuse each W load 4x)
    u64 oacc[4][4][2];
#pragma unroll
    for (int g = 0; g < 4; ++g)
#pragma unroll
        for (int m = 0; m < 4; ++m) { oacc[g][m][0] = 0ull; oacc[g][m][1] = 0ull; }

#pragma unroll 4
    for (int d = 0; d < KD; ++d) {
        const float* wr = sWvT + d * 68 + sub * 4;
        u64 w2[4][2];
#pragma unroll
        for (int m = 0; m < 4; ++m) {
            float4 wv = *(const float4*)(wr + m * 16);
            w2[m][0] = pack2(wv.x, wv.y);
            w2[m][1] = pack2(wv.z, wv.w);
        }
#pragma unroll
        for (int g = 0; g < 4; ++g) {
            float sv = sS[(g * 64 + row64) * 68 + d];
            u64 ss = pack2(sv, sv);
#pragma unroll
            for (int m = 0; m < 4; ++m) {
                oacc[g][m][0] = ffma2(ss, w2[m][0], oacc[g][m][0]);
                oacc[g][m][1] = ffma2(ss, w2[m][1], oacc[g][m][1]);
            }
        }
    }

    // Stage 5: LayerNorm + output
    float4 g4[4], be4[4];
#pragma unroll
    for (int m = 0; m < 4; ++m) {
        g4[m]  = *(const float4*)(gamma + sub * 4 + m * 16);
        be4[m] = *(const float4*)(beta  + sub * 4 + m * 16);
    }

#pragma unroll
    for (int g = 0; g < 4; ++g) {
        float ov[4][4];
#pragma unroll
        for (int m = 0; m < 4; ++m) {
            unpack2(oacc[g][m][0], ov[m][0], ov[m][1]);
            unpack2(oacc[g][m][1], ov[m][2], ov[m][3]);
        }
        float lsum = 0.0f, lsq = 0.0f;
#pragma unroll
        for (int m = 0; m < 4; ++m)
#pragma unroll
            for (int e = 0; e < 4; ++e) {
                lsum += ov[m][e];
                lsq = fmaf(ov[m][e], ov[m][e], lsq);
            }
        lsum += __shfl_xor_sync(0xffffffffu, lsum, 1);
        lsum += __shfl_xor_sync(0xffffffffu, lsum, 2);
        lsq  += __shfl_xor_sync(0xffffffffu, lsq, 1);
        lsq  += __shfl_xor_sync(0xffffffffu, lsq, 2);
        const float mean = lsum * (1.0f / 64.0f);
        const float var  = lsq * (1.0f / 64.0f) - mean * mean;
        const float inv  = rsqrtf(var + LN_EPS);

        const size_t b = b0 + g * 64 + row64;
        float* op = out + b * KD + sub * 4;
#pragma unroll
        for (int m = 0; m < 4; ++m) {
            float4 res;
            res.x = fmaf((ov[m][0] - mean) * inv, g4[m].x, be4[m].x);
            res.y = fmaf((ov[m][1] - mean) * inv, g4[m].y, be4[m].y);
            res.z = fmaf((ov[m][2] - mean) * inv, g4[m].z, be4[m].z);
            res.w = fmaf((ov[m][3] - mean) * inv, g4[m].w, be4[m].w);
            *(float4*)(op + m * 16) = res;
        }
    }
}

// ---------------- launch ----------------
extern "C" void kernel_launch(void* const* d_in, const int* in_sizes, int n_in,
                              void* d_out, int out_size) {
    const float* query = (const float*)d_in[0];
    const float* kv    = (const float*)d_in[1];
    const float* w_q   = (const float*)d_in[2];
    const float* w_k   = (const float*)d_in[3];
    const float* w_v   = (const float*)d_in[4];
    const float* gamma = (const float*)d_in[5];
    const float* beta  = (const float*)d_in[6];
    float* out = (float*)d_out;

    const int smem_bytes = SMEM_FLOATS * sizeof(float);   // 87040
    cudaFuncSetAttribute(lca_main, cudaFuncAttributeMaxDynamicSharedMemorySize, smem_bytes);

    lca_compute_M<<<QD, KD>>>(w_q, w_k);
    lca_main<<<B_TOTAL / RB, THREADS, smem_bytes>>>(query, kv, w_v, gamma, beta, out);
}

// round 3
// speedup vs baseline: 4.3656x; 1.0969x over previous
#include <cuda_runtime.h>
#include <cstdint>

#define QD        512
#define KD        64
#define NAUX      8
#define B_TOTAL   65536
#define LN_EPS    1e-5f

#define RB        256        // batch rows per block
#define THREADS   256
#define IC        32         // i-chunk size
#define NCH       (QD / IC)  // 16 chunks

typedef unsigned long long u64;

// ---------------- f32x2 packed-math helpers (sm_103a) ----------------
__device__ __forceinline__ u64 ffma2(u64 a, u64 b, u64 c) {
    u64 d;
    asm("fma.rn.f32x2 %0, %1, %2, %3;" : "=l"(d) : "l"(a), "l"(b), "l"(c));
    return d;
}
__device__ __forceinline__ u64 pack2(float lo, float hi) {
    u64 r;
    asm("mov.b64 %0, {%1, %2};" : "=l"(r) : "f"(lo), "f"(hi));
    return r;
}
__device__ __forceinline__ void unpack2(u64 v, float& lo, float& hi) {
    asm("mov.b64 {%0, %1}, %2;" : "=f"(lo), "=f"(hi) : "l"(v));
}
__device__ __forceinline__ void cp16(uint32_t dst, const void* src) {
    asm volatile("cp.async.cg.shared.global [%0], [%1], 16;" :: "r"(dst), "l"(src));
}

// M = W_q^T @ W_k  (512 x 64 row-major), 128 KB scratch.
__device__ __align__(256) float g_M[QD * KD];

__global__ void lca_compute_M(const float* __restrict__ w_q,
                              const float* __restrict__ w_k) {
    const int j  = threadIdx.x & 63;
    const int il = threadIdx.x >> 6;          // 0..3
    const int i  = blockIdx.x * 4 + il;       // 0..511
    float acc = 0.0f;
#pragma unroll
    for (int e = 0; e < KD; ++e)
        acc = fmaf(w_q[e * QD + i], w_k[e * KD + j], acc);
    g_M[i * KD + j] = acc;
}

// Smem (floats):
//   sQ buf0/buf1: [0,8192) [8192,16384)      row-major 256x32, f4-col XOR swizzle
//   sM buf0/buf1: [16384,18432) [18432,20480) 32x64 plain
//   sWvT:         [20480,24832)               64x68 transposed W_v
//   Phase B: sQM/sS 256x68 = 17408 floats alias [0,17408)
#define SMEM_FLOATS 24832

__global__ void __launch_bounds__(THREADS, 2)
lca_main(const float* __restrict__ query,
         const float* __restrict__ kv,
         const float* __restrict__ w_v,
         const float* __restrict__ gamma,
         const float* __restrict__ beta,
         float* __restrict__ out) {
    extern __shared__ float smem[];
    const int tid = threadIdx.x;
    const int ct  = tid & 7;             // col tile: ct*4..+3 and 32+ct*4..+3
    const int rt  = tid >> 3;            // row tile: rows rt*8..rt*8+7
    const int b0  = blockIdx.x * RB;
    const uint32_t su = (uint32_t)__cvta_generic_to_shared(smem);

    float* sWvT = smem + 20480;
    for (int idx = tid; idx < KD * KD; idx += THREADS) {
        int e = idx >> 6, d = idx & 63;
        sWvT[d * 68 + e] = w_v[idx];
    }

    u64 acc[8][4];
#pragma unroll
    for (int r = 0; r < 8; ++r)
#pragma unroll
        for (int c = 0; c < 4; ++c) acc[r][c] = 0ull;

    // ---- async chunk loader (q row-major w/ f4-col swizzle, M plain) ----
    auto load_chunk = [&](int ch, int bi) {
        const int i0 = ch * IC;
#pragma unroll
        for (int p = 0; p < 8; ++p) {
            int idx = p * THREADS + tid;            // 0..2047
            int r   = idx >> 3;                     // 0..255
            int c4  = idx & 7;                      // f4 col
            int swz = c4 ^ ((r >> 3) & 7);
            uint32_t dst = su + (uint32_t)(bi * 8192 + r * 32 + swz * 4) * 4u;
            cp16(dst, query + (size_t)(b0 + r) * QD + i0 + c4 * 4);
        }
#pragma unroll
        for (int p = 0; p < 2; ++p) {
            int idx = p * THREADS + tid;            // 0..511 (f4 units)
            uint32_t dst = su + (uint32_t)(16384 + bi * 2048 + idx * 4) * 4u;
            cp16(dst, g_M + i0 * KD + idx * 4);
        }
        asm volatile("cp.async.commit_group;");
    };

    load_chunk(0, 0);

    const int s = rt & 7;
#pragma unroll 1
    for (int ch = 0; ch < NCH; ++ch) {
        if (ch + 1 < NCH) {
            load_chunk(ch + 1, (ch + 1) & 1);
            asm volatile("cp.async.wait_group 1;");
        } else {
            asm volatile("cp.async.wait_group 0;");
        }
        __syncthreads();

        const int bi = ch & 1;
        const float* qb = smem + bi * 8192 + rt * 256;       // rows rt*8.., pitch 32
        const float* mb = smem + 16384 + bi * 2048 + ct * 4;

#pragma unroll
        for (int g4 = 0; g4 < 8; ++g4) {
            const float* qcol = qb + ((g4 ^ s) << 2);
#pragma unroll
            for (int h = 0; h < 2; ++h) {
                float4 qv[4];
#pragma unroll
                for (int rr = 0; rr < 4; ++rr)
                    qv[rr] = *(const float4*)(qcol + (h * 4 + rr) * 32);
#pragma unroll
                for (int i = 0; i < 4; ++i) {
                    const float* mp = mb + (g4 * 4 + i) * 64;
                    ulonglong2 mlo = *(const ulonglong2*)mp;
                    ulonglong2 mhi = *(const ulonglong2*)(mp + 32);
#pragma unroll
                    for (int rr = 0; rr < 4; ++rr) {
                        float qs = (i == 0) ? qv[rr].x : (i == 1) ? qv[rr].y
                                 : (i == 2) ? qv[rr].z : qv[rr].w;
                        u64 qq = pack2(qs, qs);
                        int r = h * 4 + rr;
                        acc[r][0] = ffma2(qq, mlo.x, acc[r][0]);
                        acc[r][1] = ffma2(qq, mlo.y, acc[r][1]);
                        acc[r][2] = ffma2(qq, mhi.x, acc[r][2]);
                        acc[r][3] = ffma2(qq, mhi.y, acc[r][3]);
                    }
                }
            }
        }
        __syncthreads();
    }

    // ---- hand off qm (pitch 68) ----
    float* sQM = smem;
#pragma unroll
    for (int r = 0; r < 8; ++r) {
        float4 lo, hi;
        unpack2(acc[r][0], lo.x, lo.y); unpack2(acc[r][1], lo.z, lo.w);
        unpack2(acc[r][2], hi.x, hi.y); unpack2(acc[r][3], hi.z, hi.w);
        float* dst = sQM + (rt * 8 + r) * 68 + ct * 4;
        *(float4*)dst        = lo;
        *(float4*)(dst + 32) = hi;
    }
    __syncthreads();

    // ---------------- Epilogue: attention + W_v + LayerNorm ----------------
    const int sub   = tid & 3;
    const int row64 = tid >> 2;
    float* sS = smem;   // aliases sQM row-exactly

    for (int g = 0; g < 4; ++g) {
        const int r = g * 64 + row64;
        const size_t b = b0 + r;

        float4 qmv[4];
#pragma unroll
        for (int m = 0; m < 4; ++m)
            qmv[m] = *(const float4*)(sQM + r * 68 + sub * 4 + m * 16);

        const float* kvb = kv + b * (NAUX * KD) + sub * 4;

        float sc[NAUX];
#pragma unroll
        for (int n = 0; n < NAUX; ++n) {
            float p = 0.0f;
#pragma unroll
            for (int m = 0; m < 4; ++m) {
                float4 a = *(const float4*)(kvb + n * KD + m * 16);
                p = fmaf(a.x, qmv[m].x, p);
                p = fmaf(a.y, qmv[m].y, p);
                p = fmaf(a.z, qmv[m].z, p);
                p = fmaf(a.w, qmv[m].w, p);
            }
            sc[n] = p;
        }
#pragma unroll
        for (int n = 0; n < NAUX; ++n) {
            sc[n] += __shfl_xor_sync(0xffffffffu, sc[n], 1);
            sc[n] += __shfl_xor_sync(0xffffffffu, sc[n], 2);
            sc[n] *= 0.125f;           // KV_DIM^-0.5
        }
        float mx = sc[0];
#pragma unroll
        for (int n = 1; n < NAUX; ++n) mx = fmaxf(mx, sc[n]);
        float attn[NAUX], ssum = 0.0f;
#pragma unroll
        for (int n = 0; n < NAUX; ++n) { attn[n] = __expf(sc[n] - mx); ssum += attn[n]; }
        float rs = 1.0f / ssum;

        float s16[4][4];
#pragma unroll
        for (int m = 0; m < 4; ++m)
#pragma unroll
            for (int e = 0; e < 4; ++e) s16[m][e] = 0.0f;
#pragma unroll
        for (int n = 0; n < NAUX; ++n) {
            float w = attn[n] * rs;
#pragma unroll
            for (int m = 0; m < 4; ++m) {
                float4 a = *(const float4*)(kvb + n * KD + m * 16);   // L1 hit
                s16[m][0] = fmaf(w, a.x, s16[m][0]);
                s16[m][1] = fmaf(w, a.y, s16[m][1]);
                s16[m][2] = fmaf(w, a.z, s16[m][2]);
                s16[m][3] = fmaf(w, a.w, s16[m][3]);
            }
        }
#pragma unroll
        for (int m = 0; m < 4; ++m)
            *(float4*)(sS + r * 68 + sub * 4 + m * 16) =
                make_float4(s16[m][0], s16[m][1], s16[m][2], s16[m][3]);
    }
    __syncwarp();

    // Stage 4: o = W_v @ s for 4 rows at once
    u64 oacc[4][4][2];
#pragma unroll
    for (int g = 0; g < 4; ++g)
#pragma unroll
        for (int m = 0; m < 4; ++m) { oacc[g][m][0] = 0ull; oacc[g][m][1] = 0ull; }

#pragma unroll 4
    for (int d = 0; d < KD; ++d) {
        const float* wr = sWvT + d * 68 + sub * 4;
        u64 w2[4][2];
#pragma unroll
        for (int m = 0; m < 4; ++m) {
            float4 wv = *(const float4*)(wr + m * 16);
            w2[m][0] = pack2(wv.x, wv.y);
            w2[m][1] = pack2(wv.z, wv.w);
        }
#pragma unroll
        for (int g = 0; g < 4; ++g) {
            float sv = sS[(g * 64 + row64) * 68 + d];
            u64 ss = pack2(sv, sv);
#pragma unroll
            for (int m = 0; m < 4; ++m) {
                oacc[g][m][0] = ffma2(ss, w2[m][0], oacc[g][m][0]);
                oacc[g][m][1] = ffma2(ss, w2[m][1], oacc[g][m][1]);
            }
        }
    }

    // Stage 5: LayerNorm + output
    float4 g4v[4], be4[4];
#pragma unroll
    for (int m = 0; m < 4; ++m) {
        g4v[m] = *(const float4*)(gamma + sub * 4 + m * 16);
        be4[m] = *(const float4*)(beta  + sub * 4 + m * 16);
    }

#pragma unroll
    for (int g = 0; g < 4; ++g) {
        float ov[4][4];
#pragma unroll
        for (int m = 0; m < 4; ++m) {
            unpack2(oacc[g][m][0], ov[m][0], ov[m][1]);
            unpack2(oacc[g][m][1], ov[m][2], ov[m][3]);
        }
        float lsum = 0.0f, lsq = 0.0f;
#pragma unroll
        for (int m = 0; m < 4; ++m)
#pragma unroll
            for (int e = 0; e < 4; ++e) {
                lsum += ov[m][e];
                lsq = fmaf(ov[m][e], ov[m][e], lsq);
            }
        lsum += __shfl_xor_sync(0xffffffffu, lsum, 1);
        lsum += __shfl_xor_sync(0xffffffffu, lsum, 2);
        lsq  += __shfl_xor_sync(0xffffffffu, lsq, 1);
        lsq  += __shfl_xor_sync(0xffffffffu, lsq, 2);
        const float mean = lsum * (1.0f / 64.0f);
        const float var  = lsq * (1.0f / 64.0f) - mean * mean;
        const float inv  = rsqrtf(var + LN_EPS);

        const size_t b = b0 + g * 64 + row64;
        float* op = out + b * KD + sub * 4;
#pragma unroll
        for (int m = 0; m < 4; ++m) {
            float4 res;
            res.x = fmaf((ov[m][0] - mean) * inv, g4v[m].x, be4[m].x);
            res.y = fmaf((ov[m][1] - mean) * inv, g4v[m].y, be4[m].y);
            res.z = fmaf((ov[m][2] - mean) * inv, g4v[m].z, be4[m].z);
            res.w = fmaf((ov[m][3] - mean) * inv, g4v[m].w, be4[m].w);
            *(float4*)(op + m * 16) = res;
        }
    }
}

// ---------------- launch ----------------
extern "C" void kernel_launch(void* const* d_in, const int* in_sizes, int n_in,
                              void* d_out, int out_size) {
    const float* query = (const float*)d_in[0];
    const float* kv    = (const float*)d_in[1];
    const float* w_q   = (const float*)d_in[2];
    const float* w_k   = (const float*)d_in[3];
    const float* w_v   = (const float*)d_in[4];
    const float* gamma = (const float*)d_in[5];
    const float* beta  = (const float*)d_in[6];
    float* out = (float*)d_out;

    const int smem_bytes = SMEM_FLOATS * sizeof(float);   // 99328
    cudaFuncSetAttribute(lca_main, cudaFuncAttributeMaxDynamicSharedMemorySize, smem_bytes);

    lca_compute_M<<<QD / 4, THREADS>>>(w_q, w_k);
    lca_main<<<B_TOTAL / RB, THREADS, smem_bytes>>>(query, kv, w_v, gamma, beta, out);
}

// round 5
// speedup vs baseline: 5.4228x; 1.2422x over previous
#include <cuda_runtime.h>
#include <cuda_bf16.h>
#include <cstdint>

#define QD        512
#define KD        64
#define NAUX      8
#define B_TOTAL   65536
#define LN_EPS    1e-5f

#define THREADS   256
#define RB        128              // rows per CTA
#define KC        64               // K-chunk
#define NCH       (QD / KC)        // 8 chunks

// smem byte offsets
#define AH_OFF    0                // Ahi: 128 rows x 72 halves = 18432 B
#define AL_OFF    18432            // Alo: 18432 B
#define BH_OFF    36864            // Bhi: 64 x 72 halves = 9216 B
#define BL_OFF    46080            // Blo: 9216 B
#define WVT_OFF   55296            // sWvT: 64x68 f32 = 17408 B
#define SMEM_BYTES 72704
#define SQM_OFF_F 0                // sQM aliases A region: 128x68 f32 = 34816 B

typedef unsigned long long u64;

__device__ __forceinline__ u64 pack2(float lo, float hi) {
    u64 r; asm("mov.b64 %0, {%1, %2};" : "=l"(r) : "f"(lo), "f"(hi)); return r;
}
__device__ __forceinline__ void unpack2(u64 v, float& lo, float& hi) {
    asm("mov.b64 {%0, %1}, %2;" : "=f"(lo), "=f"(hi) : "l"(v));
}
__device__ __forceinline__ u64 ffma2(u64 a, u64 b, u64 c) {
    u64 d; asm("fma.rn.f32x2 %0, %1, %2, %3;" : "=l"(d) : "l"(a), "l"(b), "l"(c)); return d;
}
__device__ __forceinline__ void cp16(uint32_t dst, const void* src) {
    asm volatile("cp.async.cg.shared.global [%0], [%1], 16;" :: "r"(dst), "l"(src));
}
__device__ __forceinline__ uint32_t cvt_bf2(float hi, float lo) {
    uint32_t r;
    asm("cvt.rn.bf16x2.f32 %0, %1, %2;" : "=r"(r) : "f"(hi), "f"(lo));
    return r;
}
__device__ __forceinline__ void mma_bf16(float* c, uint32_t a0, uint32_t a1,
                                         uint32_t a2, uint32_t a3,
                                         uint32_t b0, uint32_t b1) {
    asm volatile(
        "mma.sync.aligned.m16n8k16.row.col.f32.bf16.bf16.f32 "
        "{%0,%1,%2,%3}, {%4,%5,%6,%7}, {%8,%9}, {%0,%1,%2,%3};"
        : "+f"(c[0]), "+f"(c[1]), "+f"(c[2]), "+f"(c[3])
        : "r"(a0), "r"(a1), "r"(a2), "r"(a3), "r"(b0), "r"(b1));
}
__device__ __forceinline__ void ldsm4(uint32_t& r0, uint32_t& r1, uint32_t& r2,
                                      uint32_t& r3, uint32_t addr) {
    asm volatile("ldmatrix.sync.aligned.m8n8.x4.shared.b16 {%0,%1,%2,%3}, [%4];"
                 : "=r"(r0), "=r"(r1), "=r"(r2), "=r"(r3) : "r"(addr));
}

// B operand: M^T split into bf16 hi/lo.  g_B*[n*QD + k]
__device__ __align__(256) __nv_bfloat16 g_Bhi[KD * QD];
__device__ __align__(256) __nv_bfloat16 g_Blo[KD * QD];

__global__ void lca_compute_M(const float* __restrict__ w_q,
                              const float* __restrict__ w_k) {
    const int j  = threadIdx.x & 63;
    const int il = threadIdx.x >> 6;
    const int i  = blockIdx.x * 4 + il;       // 0..511
    float acc = 0.0f;
#pragma unroll
    for (int e = 0; e < KD; ++e)
        acc = fmaf(w_q[e * QD + i], w_k[e * KD + j], acc);
    __nv_bfloat16 h = __float2bfloat16_rn(acc);
    __nv_bfloat16 l = __float2bfloat16_rn(acc - __bfloat162float(h));
    g_Bhi[j * QD + i] = h;
    g_Blo[j * QD + i] = l;
}

__global__ void __launch_bounds__(THREADS, 2)
lca_main(const float* __restrict__ query,
         const float* __restrict__ kv,
         const float* __restrict__ w_v,
         const float* __restrict__ gamma,
         const float* __restrict__ beta,
         float* __restrict__ out) {
    extern __shared__ float smem[];
    char* smc = (char*)smem;
    const uint32_t su = (uint32_t)__cvta_generic_to_shared(smem);
    const int tid  = threadIdx.x;
    const int wid  = tid >> 5;
    const int lane = tid & 31;
    const int b0   = blockIdx.x * RB;

    // persistent: transposed W_v (region disjoint from A/B buffers)
    float* sWvT = (float*)(smc + WVT_OFF);
    for (int idx = tid; idx < KD * KD; idx += THREADS) {
        int e = idx >> 6, d = idx & 63;
        sWvT[d * 68 + e] = w_v[idx];
    }

    float C[8][4];
#pragma unroll
    for (int t = 0; t < 8; ++t)
#pragma unroll
        for (int c = 0; c < 4; ++c) C[t][c] = 0.0f;

    const int rw   = wid * 16;           // warp's row base
    const int g    = lane >> 2;          // 0..7
    const int kcol = (lane & 3) * 2;

    // ---------------- Mainloop: qm = query @ M  (HMMA bf16-split) ----------------
    for (int ch = 0; ch < NCH; ++ch) {
        const int i0 = ch * KC;
        __syncthreads();   // previous chunk's reads complete

        // B chunk via cp.async: hi/lo, [n][k] pitch 72 halves (144 B)
#pragma unroll
        for (int p = 0; p < 2; ++p) {
            int idx = p * THREADS + tid;          // 0..511
            int n = idx >> 3, k8 = idx & 7;
            cp16(su + BH_OFF + n * 144 + k8 * 16,
                 (const char*)g_Bhi + (size_t)n * 1024 + i0 * 2 + k8 * 16);
            cp16(su + BL_OFF + n * 144 + k8 * 16,
                 (const char*)g_Blo + (size_t)n * 1024 + i0 * 2 + k8 * 16);
        }
        asm volatile("cp.async.commit_group;");

        // A chunk: LDG fp32 -> bf16 hi/lo -> STS, pitch 72 halves
        {
            float4 v[8];
#pragma unroll
            for (int p = 0; p < 8; ++p) {
                int idx = p * THREADS + tid;      // 0..2047
                int r = idx >> 4, c4 = idx & 15;
                v[p] = *(const float4*)(query + (size_t)(b0 + r) * QD + i0 + c4 * 4);
            }
#pragma unroll
            for (int p = 0; p < 8; ++p) {
                int idx = p * THREADS + tid;
                int r = idx >> 4, c4 = idx & 15;
                uint32_t h01 = cvt_bf2(v[p].y, v[p].x);
                uint32_t h23 = cvt_bf2(v[p].w, v[p].z);
                float hx = __uint_as_float(h01 << 16);
                float hy = __uint_as_float(h01 & 0xffff0000u);
                float hz = __uint_as_float(h23 << 16);
                float hw = __uint_as_float(h23 & 0xffff0000u);
                uint32_t l01 = cvt_bf2(v[p].y - hy, v[p].x - hx);
                uint32_t l23 = cvt_bf2(v[p].w - hw, v[p].z - hz);
                uint2 hq = make_uint2(h01, h23);
                uint2 lq = make_uint2(l01, l23);
                *(uint2*)(smc + AH_OFF + r * 144 + c4 * 8) = hq;
                *(uint2*)(smc + AL_OFF + r * 144 + c4 * 8) = lq;
            }
        }
        asm volatile("cp.async.wait_group 0;");
        __syncthreads();

        // compute: 4 k16 steps
#pragma unroll
        for (int kk = 0; kk < 4; ++kk) {
            const int k0 = kk * 16;
            // A frags (LDS.32 of bf16x2), conflict-free
            uint32_t ah0 = *(const uint32_t*)(smc + AH_OFF + (rw + g)     * 144 + (k0 + kcol) * 2);
            uint32_t ah1 = *(const uint32_t*)(smc + AH_OFF + (rw + g + 8) * 144 + (k0 + kcol) * 2);
            uint32_t ah2 = *(const uint32_t*)(smc + AH_OFF + (rw + g)     * 144 + (k0 + kcol + 8) * 2);
            uint32_t ah3 = *(const uint32_t*)(smc + AH_OFF + (rw + g + 8) * 144 + (k0 + kcol + 8) * 2);
            uint32_t al0 = *(const uint32_t*)(smc + AL_OFF + (rw + g)     * 144 + (k0 + kcol) * 2);
            uint32_t al1 = *(const uint32_t*)(smc + AL_OFF + (rw + g + 8) * 144 + (k0 + kcol) * 2);
            uint32_t al2 = *(const uint32_t*)(smc + AL_OFF + (rw + g)     * 144 + (k0 + kcol + 8) * 2);
            uint32_t al3 = *(const uint32_t*)(smc + AL_OFF + (rw + g + 8) * 144 + (k0 + kcol + 8) * 2);

#pragma unroll
            for (int j = 0; j < 4; ++j) {
                // ldmatrix rows: nrow = j*16 + lane%8 + (lane>=16 ? 8 : 0); khalf = (lane>>3)&1
                uint32_t nrow  = j * 16 + (lane & 7) + ((lane >> 4) << 3);
                uint32_t khalf = (lane >> 3) & 1;
                uint32_t aoff  = nrow * 144 + khalf * 16 + k0 * 2;
                uint32_t bh0, bh1, bh2, bh3, bl0, bl1, bl2, bl3;
                ldsm4(bh0, bh1, bh2, bh3, su + BH_OFF + aoff);
                ldsm4(bl0, bl1, bl2, bl3, su + BL_OFF + aoff);
                mma_bf16(C[2*j],   ah0, ah1, ah2, ah3, bh0, bh1);
                mma_bf16(C[2*j],   ah0, ah1, ah2, ah3, bl0, bl1);
                mma_bf16(C[2*j],   al0, al1, al2, al3, bh0, bh1);
                mma_bf16(C[2*j+1], ah0, ah1, ah2, ah3, bh2, bh3);
                mma_bf16(C[2*j+1], ah0, ah1, ah2, ah3, bl2, bl3);
                mma_bf16(C[2*j+1], al0, al1, al2, al3, bh2, bh3);
            }
        }
    }
    __syncthreads();   // done reading A/B smem; safe to overwrite with sQM

    // ---- write qm to smem (pitch 68) ----
    float* sQM = smem + SQM_OFF_F;
#pragma unroll
    for (int t = 0; t < 8; ++t) {
        float* d0 = sQM + (rw + g) * 68     + t * 8 + kcol;
        float* d1 = sQM + (rw + g + 8) * 68 + t * 8 + kcol;
        *(float2*)d0 = make_float2(C[t][0], C[t][1]);
        *(float2*)d1 = make_float2(C[t][2], C[t][3]);
    }
    __syncthreads();

    // ---------------- Epilogue: attention + W_v + LayerNorm ----------------
    const int sub   = tid & 3;
    const int row32 = tid >> 2;          // 0..63
    float* sS = sQM;                     // row-exact alias

    for (int gg = 0; gg < 2; ++gg) {
        const int r = gg * 64 + row32;
        const size_t b = b0 + r;

        float4 qmv[4];
#pragma unroll
        for (int m = 0; m < 4; ++m)
            qmv[m] = *(const float4*)(sQM + r * 68 + sub * 4 + m * 16);

        const float* kvb = kv + b * (NAUX * KD) + sub * 4;

        float sc[NAUX];
#pragma unroll
        for (int n = 0; n < NAUX; ++n) {
            float p = 0.0f;
#pragma unroll
            for (int m = 0; m < 4; ++m) {
                float4 a = *(const float4*)(kvb + n * KD + m * 16);
                p = fmaf(a.x, qmv[m].x, p);
                p = fmaf(a.y, qmv[m].y, p);
                p = fmaf(a.z, qmv[m].z, p);
                p = fmaf(a.w, qmv[m].w, p);
            }
            sc[n] = p;
        }
#pragma unroll
        for (int n = 0; n < NAUX; ++n) {
            sc[n] += __shfl_xor_sync(0xffffffffu, sc[n], 1);
            sc[n] += __shfl_xor_sync(0xffffffffu, sc[n], 2);
            sc[n] *= 0.125f;
        }
        float mx = sc[0];
#pragma unroll
        for (int n = 1; n < NAUX; ++n) mx = fmaxf(mx, sc[n]);
        float attn[NAUX], ssum = 0.0f;
#pragma unroll
        for (int n = 0; n < NAUX; ++n) { attn[n] = __expf(sc[n] - mx); ssum += attn[n]; }
        float rs = 1.0f / ssum;

        float s16[4][4];
#pragma unroll
        for (int m = 0; m < 4; ++m)
#pragma unroll
            for (int e = 0; e < 4; ++e) s16[m][e] = 0.0f;
#pragma unroll
        for (int n = 0; n < NAUX; ++n) {
            float w = attn[n] * rs;
#pragma unroll
            for (int m = 0; m < 4; ++m) {
                float4 a = *(const float4*)(kvb + n * KD + m * 16);   // L1 hit
                s16[m][0] = fmaf(w, a.x, s16[m][0]);
                s16[m][1] = fmaf(w, a.y, s16[m][1]);
                s16[m][2] = fmaf(w, a.z, s16[m][2]);
                s16[m][3] = fmaf(w, a.w, s16[m][3]);
            }
        }
#pragma unroll
        for (int m = 0; m < 4; ++m)
            *(float4*)(sS + r * 68 + sub * 4 + m * 16) =
                make_float4(s16[m][0], s16[m][1], s16[m][2], s16[m][3]);
    }
    __syncwarp();

    // Stage 4: o = W_v @ s for 2 rows at once
    u64 oacc[2][4][2];
#pragma unroll
    for (int gg = 0; gg < 2; ++gg)
#pragma unroll
        for (int m = 0; m < 4; ++m) { oacc[gg][m][0] = 0ull; oacc[gg][m][1] = 0ull; }

#pragma unroll 4
    for (int d = 0; d < KD; ++d) {
        const float* wr = sWvT + d * 68 + sub * 4;
        u64 w2[4][2];
#pragma unroll
        for (int m = 0; m < 4; ++m) {
            float4 wv = *(const float4*)(wr + m * 16);
            w2[m][0] = pack2(wv.x, wv.y);
            w2[m][1] = pack2(wv.z, wv.w);
        }
#pragma unroll
        for (int gg = 0; gg < 2; ++gg) {
            float sv = sS[(gg * 64 + row32) * 68 + d];
            u64 ss = pack2(sv, sv);
#pragma unroll
            for (int m = 0; m < 4; ++m) {
                oacc[gg][m][0] = ffma2(ss, w2[m][0], oacc[gg][m][0]);
                oacc[gg][m][1] = ffma2(ss, w2[m][1], oacc[gg][m][1]);
            }
        }
    }

    // Stage 5: LayerNorm + output
    float4 g4v[4], be4[4];
#pragma unroll
    for (int m = 0; m < 4; ++m) {
        g4v[m] = *(const float4*)(gamma + sub * 4 + m * 16);
        be4[m] = *(const float4*)(beta  + sub * 4 + m * 16);
    }
#pragma unroll
    for (int gg = 0; gg < 2; ++gg) {
        float ov[4][4];
#pragma unroll
        for (int m = 0; m < 4; ++m) {
            unpack2(oacc[gg][m][0], ov[m][0], ov[m][1]);
            unpack2(oacc[gg][m][1], ov[m][2], ov[m][3]);
        }
        float lsum = 0.0f, lsq = 0.0f;
#pragma unroll
        for (int m = 0; m < 4; ++m)
#pragma unroll
            for (int e = 0; e < 4; ++e) {
                lsum += ov[m][e];
                lsq = fmaf(ov[m][e], ov[m][e], lsq);
            }
        lsum += __shfl_xor_sync(0xffffffffu, lsum, 1);
        lsum += __shfl_xor_sync(0xffffffffu, lsum, 2);
        lsq  += __shfl_xor_sync(0xffffffffu, lsq, 1);
        lsq  += __shfl_xor_sync(0xffffffffu, lsq, 2);
        const float mean = lsum * (1.0f / 64.0f);
        const float var  = lsq * (1.0f / 64.0f) - mean * mean;
        const float inv  = rsqrtf(var + LN_EPS);

        const size_t b = b0 + gg * 64 + row32;
        float* op = out + b * KD + sub * 4;
#pragma unroll
        for (int m = 0; m < 4; ++m) {
            float4 res;
            res.x = fmaf((ov[m][0] - mean) * inv, g4v[m].x, be4[m].x);
            res.y = fmaf((ov[m][1] - mean) * inv, g4v[m].y, be4[m].y);
            res.z = fmaf((ov[m][2] - mean) * inv, g4v[m].z, be4[m].z);
            res.w = fmaf((ov[m][3] - mean) * inv, g4v[m].w, be4[m].w);
            *(float4*)(op + m * 16) = res;
        }
    }
}

// ---------------- launch ----------------
extern "C" void kernel_launch(void* const* d_in, const int* in_sizes, int n_in,
                              void* d_out, int out_size) {
    const float* query = (const float*)d_in[0];
    const float* kv    = (const float*)d_in[1];
    const float* w_q   = (const float*)d_in[2];
    const float* w_k   = (const float*)d_in[3];
    const float* w_v   = (const float*)d_in[4];
    const float* gamma = (const float*)d_in[5];
    const float* beta  = (const float*)d_in[6];
    float* out = (float*)d_out;

    cudaFuncSetAttribute(lca_main, cudaFuncAttributeMaxDynamicSharedMemorySize, SMEM_BYTES);

    lca_compute_M<<<QD / 4, 256>>>(w_q, w_k);
    lca_main<<<B_TOTAL / RB, THREADS, SMEM_BYTES>>>(query, kv, w_v, gamma, beta, out);
}